// round 1
// baseline (speedup 1.0000x reference)
#include <cuda_runtime.h>
#include <math.h>

#define SS   1024
#define CS   768
#define CZ   128
#define HN   24
#define DD   32
#define NB   2
#define LEPS 1e-5f
#define NINF 1.0e9f

// ---------------- device scratch ----------------
__device__ float g_emb[NB * 3 * CS];            // shift|scale|gate per batch
__device__ float g_bsn[NB * SS * CS];
__device__ float g_q  [NB * SS * CS];
__device__ float g_k  [NB * SS * CS];
__device__ float g_v  [NB * SS * CS];
__device__ float g_attn[NB * SS * CS];
__device__ float g_bias[(size_t)HN * SS * SS];  // includes mask (-1e9)

// ---------------- adaLN embedding ----------------
// emb[b, j] = silu(t[b]) @ w_adaln[:, j] + b_adaln[j]
__global__ void k_adaln(const float* __restrict__ t,
                        const float* __restrict__ w,
                        const float* __restrict__ bvec) {
    __shared__ float st[CS];
    int b = blockIdx.y;
    for (int c = threadIdx.x; c < CS; c += blockDim.x) {
        float x = t[b * CS + c];
        st[c] = x / (1.f + __expf(-x));
    }
    __syncthreads();
    int j = blockIdx.x * blockDim.x + threadIdx.x;
    if (j < 3 * CS) {
        float acc = bvec[j];
        for (int c = 0; c < CS; c++)
            acc += st[c] * w[(size_t)c * (3 * CS) + j];
        g_emb[b * 3 * CS + j] = acc;
    }
}

// ---------------- bs LayerNorm + adaLN modulation ----------------
__global__ void k_bsnorm(const float* __restrict__ bs) {
    int row = blockIdx.x;
    int b = row / SS;
    const float* x = bs + (size_t)row * CS;
    float* y = g_bsn + (size_t)row * CS;
    __shared__ float red[32];
    float lx[3];
    float s = 0.f, ss = 0.f;
#pragma unroll
    for (int i = 0; i < 3; i++) {
        float v = x[threadIdx.x + i * 256];
        lx[i] = v; s += v; ss += v * v;
    }
#pragma unroll
    for (int off = 16; off; off >>= 1) {
        s  += __shfl_xor_sync(0xffffffffu, s,  off);
        ss += __shfl_xor_sync(0xffffffffu, ss, off);
    }
    int wi = threadIdx.x >> 5;
    if ((threadIdx.x & 31) == 0) { red[wi] = s; red[8 + wi] = ss; }
    __syncthreads();
    if (threadIdx.x < 32) {
        s  = (threadIdx.x < 8) ? red[threadIdx.x]     : 0.f;
        ss = (threadIdx.x < 8) ? red[8 + threadIdx.x] : 0.f;
#pragma unroll
        for (int off = 4; off; off >>= 1) {
            s  += __shfl_xor_sync(0xffffffffu, s,  off);
            ss += __shfl_xor_sync(0xffffffffu, ss, off);
        }
        if (threadIdx.x == 0) { red[16] = s; red[17] = ss; }
    }
    __syncthreads();
    float mu  = red[16] / (float)CS;
    float var = red[17] / (float)CS - mu * mu;
    float rs  = rsqrtf(var + LEPS);
    const float* shv = g_emb + b * 3 * CS;        // shift
    const float* scv = g_emb + b * 3 * CS + CS;   // scale
#pragma unroll
    for (int i = 0; i < 3; i++) {
        int c = threadIdx.x + i * 256;
        y[c] = (lx[i] - mu) * rs * (1.f + scv[c]) + shv[c];
    }
}

// ---------------- generic 2048x768x768 GEMM ----------------
// C = A @ B                       (mode 0)
// C = (A @ B + bvec) * gate       (mode 2, gate from g_emb per batch row)
__global__ void k_gemm(const float* __restrict__ A, const float* __restrict__ B,
                       const float* __restrict__ bvec, float* __restrict__ C,
                       int mode) {
    __shared__ float As[16][64];
    __shared__ float Bs[16][64];
    int n0 = blockIdx.x * 64, m0 = blockIdx.y * 64;
    int tid = threadIdx.x;
    int tx = tid & 15, ty = tid >> 4;
    float acc[4][4] = {};
    int am  = tid >> 2;          // 0..63
    int ak4 = (tid & 3) * 4;     // 0,4,8,12
    for (int k0 = 0; k0 < CS; k0 += 16) {
        float4 av = *(const float4*)(A + (size_t)(m0 + am) * CS + k0 + ak4);
        As[ak4 + 0][am] = av.x; As[ak4 + 1][am] = av.y;
        As[ak4 + 2][am] = av.z; As[ak4 + 3][am] = av.w;
#pragma unroll
        for (int i = 0; i < 4; i++) {
            int lin = tid + i * 256;
            int kk = lin >> 6, n = lin & 63;
            Bs[kk][n] = B[(size_t)(k0 + kk) * CS + n0 + n];
        }
        __syncthreads();
#pragma unroll
        for (int kk = 0; kk < 16; kk++) {
            float4 a = *(const float4*)&As[kk][ty * 4];
            float4 bq = *(const float4*)&Bs[kk][tx * 4];
            float a4[4] = {a.x, a.y, a.z, a.w};
            float b4[4] = {bq.x, bq.y, bq.z, bq.w};
#pragma unroll
            for (int r = 0; r < 4; r++)
#pragma unroll
                for (int c = 0; c < 4; c++)
                    acc[r][c] += a4[r] * b4[c];
        }
        __syncthreads();
    }
#pragma unroll
    for (int r = 0; r < 4; r++) {
        int m = m0 + ty * 4 + r;
        int n = n0 + tx * 4;
        float4 v;
        if (mode == 0) {
            v = make_float4(acc[r][0], acc[r][1], acc[r][2], acc[r][3]);
        } else {
            int b = m >> 10;
            const float* gate = g_emb + b * 3 * CS + 2 * CS;
            v = make_float4((acc[r][0] + bvec[n + 0]) * gate[n + 0],
                            (acc[r][1] + bvec[n + 1]) * gate[n + 1],
                            (acc[r][2] + bvec[n + 2]) * gate[n + 2],
                            (acc[r][3] + bvec[n + 3]) * gate[n + 3]);
        }
        *(float4*)(C + (size_t)m * CS + n) = v;
    }
}

// ---------------- per-head RMS norm (in place) ----------------
__global__ void k_rms(float* __restrict__ x, const float* __restrict__ w) {
    int gw = blockIdx.x * (blockDim.x >> 5) + (threadIdx.x >> 5);
    int lane = threadIdx.x & 31;
    if (gw >= NB * SS * HN) return;
    int row = gw / HN, h = gw % HN;
    size_t idx = (size_t)row * CS + h * DD + lane;
    float v = x[idx];
    float ss = v * v;
#pragma unroll
    for (int off = 16; off; off >>= 1)
        ss += __shfl_xor_sync(0xffffffffu, ss, off);
    x[idx] = v * rsqrtf(ss / (float)DD + LEPS) * w[lane];
}

// ---------------- bias: LN(z) @ w_z + mask ----------------
// one block = 64 (i,j) pairs, 128 threads
__global__ void k_bias(const float* __restrict__ z, const int* __restrict__ zmask,
                       const float* __restrict__ lnw, const float* __restrict__ lnb,
                       const float* __restrict__ wz) {
    __shared__ float sz[64 * 129];
    __shared__ float swz[CZ * HN];
    __shared__ float slnw[CZ], slnb[CZ];
    __shared__ float smu[64], srs[64];
    __shared__ float sparts[256];
    int tid = threadIdx.x;            // 128 threads
    int pairbase = blockIdx.x * 64;

    for (int i = tid; i < CZ * HN; i += 128) swz[i] = wz[i];
    if (tid < CZ) { slnw[tid] = lnw[tid]; slnb[tid] = lnb[tid]; }
#pragma unroll 4
    for (int i = 0; i < 64; i++) {
        int lin = tid + i * 128;
        int pr = lin >> 7, c = lin & 127;
        sz[pr * 129 + c] = z[(size_t)(pairbase + pr) * CZ + c];
    }
    __syncthreads();
    {   // partial sums: thread (p, half) over 64 cols
        int p = tid & 63, half = tid >> 6;
        float s = 0.f, ss = 0.f;
        const float* rowp = &sz[p * 129 + half * 64];
#pragma unroll 8
        for (int c = 0; c < 64; c++) { float v = rowp[c]; s += v; ss += v * v; }
        sparts[tid * 2] = s; sparts[tid * 2 + 1] = ss;
    }
    __syncthreads();
    if (tid < 64) {
        float s  = sparts[tid * 2]     + sparts[(tid + 64) * 2];
        float ss = sparts[tid * 2 + 1] + sparts[(tid + 64) * 2 + 1];
        float mu = s / (float)CZ;
        float var = ss / (float)CZ - mu * mu;
        smu[tid] = mu; srs[tid] = rsqrtf(var + LEPS);
    }
    __syncthreads();
    {   // normalize in place
        int p = tid & 63, half = tid >> 6;
        float mu = smu[p], rs = srs[p];
        float* rowp = &sz[p * 129 + half * 64];
#pragma unroll 8
        for (int c = 0; c < 64; c++) {
            int cc = half * 64 + c;
            rowp[c] = (rowp[c] - mu) * rs * slnw[cc] + slnb[cc];
        }
    }
    __syncthreads();
    // register-tiled GEMM: 16 pair-groups x 8 head-groups; 4 pairs x 3 heads per thread
    int pg = tid & 15, hg = tid >> 4;
    float acc[4][3] = {};
#pragma unroll 4
    for (int c = 0; c < CZ; c++) {
        float zn0 = sz[(pg +  0) * 129 + c];
        float zn1 = sz[(pg + 16) * 129 + c];
        float zn2 = sz[(pg + 32) * 129 + c];
        float zn3 = sz[(pg + 48) * 129 + c];
        float w0 = swz[c * HN + hg * 3 + 0];
        float w1 = swz[c * HN + hg * 3 + 1];
        float w2 = swz[c * HN + hg * 3 + 2];
        acc[0][0] += zn0 * w0; acc[0][1] += zn0 * w1; acc[0][2] += zn0 * w2;
        acc[1][0] += zn1 * w0; acc[1][1] += zn1 * w1; acc[1][2] += zn1 * w2;
        acc[2][0] += zn2 * w0; acc[2][1] += zn2 * w1; acc[2][2] += zn2 * w2;
        acc[3][0] += zn3 * w0; acc[3][1] += zn3 * w1; acc[3][2] += zn3 * w2;
    }
#pragma unroll
    for (int pi = 0; pi < 4; pi++) {
        int pair = pairbase + pg + pi * 16;
        float madd = (zmask[pair] > 0) ? 0.f : -NINF;
#pragma unroll
        for (int j = 0; j < 3; j++)
            g_bias[(size_t)(hg * 3 + j) * SS * SS + pair] = acc[pi][j] + madd;
    }
}

// ---------------- attention (flash-style, online softmax) ----------------
// block = (qtile 64) x (h) x (b); 256 threads (16x16)
__global__ void k_attn(const float* __restrict__ beta) {
    __shared__ float sq[64][36];
    __shared__ float sk[64][36];
    __shared__ float sv[64][33];
    __shared__ float sp[64][68];
    int qt = blockIdx.x, h = blockIdx.y, b = blockIdx.z;
    int q0 = qt * 64;
    int tid = threadIdx.x, tx = tid & 15, ty = tid >> 4;
#pragma unroll
    for (int i = 0; i < 2; i++) {
        int lin = tid + i * 256;
        int r = lin >> 3, d4 = (lin & 7) * 4;
        float4 v = *(const float4*)(g_q + (size_t)(b * SS + q0 + r) * CS + h * DD + d4);
        *(float4*)&sq[r][d4] = v;
    }
    float m[4], l[4], o[4][2];
#pragma unroll
    for (int r = 0; r < 4; r++) { m[r] = -1e30f; l[r] = 0.f; o[r][0] = 0.f; o[r][1] = 0.f; }
    const float sc = 0.17677669529663687f;   // 1/sqrt(32)

    for (int kt = 0; kt < 16; kt++) {
        int k0 = kt * 64;
        __syncthreads();
#pragma unroll
        for (int i = 0; i < 2; i++) {
            int lin = tid + i * 256;
            int r = lin >> 3, d4 = (lin & 7) * 4;
            float4 kv4 = *(const float4*)(g_k + (size_t)(b * SS + k0 + r) * CS + h * DD + d4);
            *(float4*)&sk[r][d4] = kv4;
            float4 vv4 = *(const float4*)(g_v + (size_t)(b * SS + k0 + r) * CS + h * DD + d4);
            sv[r][d4 + 0] = vv4.x; sv[r][d4 + 1] = vv4.y;
            sv[r][d4 + 2] = vv4.z; sv[r][d4 + 3] = vv4.w;
        }
        __syncthreads();
        // GEMM1: s = q @ k^T
        float s[4][4] = {};
#pragma unroll
        for (int d = 0; d < DD; d += 4) {
            float4 qv[4], kv[4];
#pragma unroll
            for (int r = 0; r < 4; r++) qv[r] = *(const float4*)&sq[ty * 4 + r][d];
#pragma unroll
            for (int c = 0; c < 4; c++) kv[c] = *(const float4*)&sk[tx * 4 + c][d];
#pragma unroll
            for (int r = 0; r < 4; r++)
#pragma unroll
                for (int c = 0; c < 4; c++)
                    s[r][c] += qv[r].x * kv[c].x + qv[r].y * kv[c].y
                             + qv[r].z * kv[c].z + qv[r].w * kv[c].w;
        }
        // scale + bias + beta
#pragma unroll
        for (int r = 0; r < 4; r++) {
            int qi = q0 + ty * 4 + r;
            float4 bz = *(const float4*)(g_bias + (size_t)h * SS * SS + (size_t)qi * SS + k0 + tx * 4);
            float4 bt = *(const float4*)(beta   + (size_t)b * SS * SS + (size_t)qi * SS + k0 + tx * 4);
            s[r][0] = s[r][0] * sc + bz.x + bt.x;
            s[r][1] = s[r][1] * sc + bz.y + bt.y;
            s[r][2] = s[r][2] * sc + bz.z + bt.z;
            s[r][3] = s[r][3] * sc + bz.w + bt.w;
        }
        // online softmax update (row = 16-lane group)
#pragma unroll
        for (int r = 0; r < 4; r++) {
            float mt = fmaxf(fmaxf(s[r][0], s[r][1]), fmaxf(s[r][2], s[r][3]));
#pragma unroll
            for (int off = 8; off; off >>= 1)
                mt = fmaxf(mt, __shfl_xor_sync(0xffffffffu, mt, off));
            float mn = fmaxf(m[r], mt);
            float alpha = __expf(m[r] - mn);
            float p0 = __expf(s[r][0] - mn);
            float p1 = __expf(s[r][1] - mn);
            float p2 = __expf(s[r][2] - mn);
            float p3 = __expf(s[r][3] - mn);
            float rsum = p0 + p1 + p2 + p3;
#pragma unroll
            for (int off = 8; off; off >>= 1)
                rsum += __shfl_xor_sync(0xffffffffu, rsum, off);
            l[r] = l[r] * alpha + rsum;
            m[r] = mn;
            o[r][0] *= alpha; o[r][1] *= alpha;
            sp[ty * 4 + r][tx * 4 + 0] = p0;
            sp[ty * 4 + r][tx * 4 + 1] = p1;
            sp[ty * 4 + r][tx * 4 + 2] = p2;
            sp[ty * 4 + r][tx * 4 + 3] = p3;
        }
        __syncthreads();
        // GEMM2: o += p @ v   (thread covers d = tx*2 .. tx*2+1)
#pragma unroll 4
        for (int kk = 0; kk < 64; kk += 4) {
            float4 pv[4];
#pragma unroll
            for (int r = 0; r < 4; r++) pv[r] = *(const float4*)&sp[ty * 4 + r][kk];
#pragma unroll
            for (int j = 0; j < 2; j++) {
                float v0 = sv[kk + 0][tx * 2 + j];
                float v1 = sv[kk + 1][tx * 2 + j];
                float v2 = sv[kk + 2][tx * 2 + j];
                float v3 = sv[kk + 3][tx * 2 + j];
#pragma unroll
                for (int r = 0; r < 4; r++)
                    o[r][j] += pv[r].x * v0 + pv[r].y * v1 + pv[r].z * v2 + pv[r].w * v3;
            }
        }
    }
    // epilogue
#pragma unroll
    for (int r = 0; r < 4; r++) {
        float inv = 1.f / l[r];
        int qi = q0 + ty * 4 + r;
        float* dst = g_attn + (size_t)(b * SS + qi) * CS + h * DD + tx * 2;
        dst[0] = o[r][0] * inv;
        dst[1] = o[r][1] * inv;
    }
}

// ---------------- launch ----------------
extern "C" void kernel_launch(void* const* d_in, const int* in_sizes, int n_in,
                              void* d_out, int out_size) {
    const float* bs      = (const float*)d_in[0];
    const float* z       = (const float*)d_in[1];
    const float* t       = (const float*)d_in[2];
    const float* beta    = (const float*)d_in[3];
    const int*   zmask   = (const int*)  d_in[4];
    const float* w_adaln = (const float*)d_in[5];
    const float* b_adaln = (const float*)d_in[6];
    const float* lnw     = (const float*)d_in[7];
    const float* lnb     = (const float*)d_in[8];
    const float* w_q     = (const float*)d_in[9];
    const float* w_k     = (const float*)d_in[10];
    const float* w_v     = (const float*)d_in[11];
    const float* w_z     = (const float*)d_in[12];
    const float* rqw     = (const float*)d_in[13];
    const float* rkw     = (const float*)d_in[14];
    const float* w_o     = (const float*)d_in[15];
    const float* b_o     = (const float*)d_in[16];
    float* out = (float*)d_out;

    float *p_bsn, *p_q, *p_k, *p_v, *p_attn;
    cudaGetSymbolAddress((void**)&p_bsn,  g_bsn);
    cudaGetSymbolAddress((void**)&p_q,    g_q);
    cudaGetSymbolAddress((void**)&p_k,    g_k);
    cudaGetSymbolAddress((void**)&p_v,    g_v);
    cudaGetSymbolAddress((void**)&p_attn, g_attn);

    k_adaln<<<dim3(9, 2), 256>>>(t, w_adaln, b_adaln);
    k_bias<<<SS * SS / 64, 128>>>(z, zmask, lnw, lnb, w_z);
    k_bsnorm<<<NB * SS, 256>>>(bs);
    k_gemm<<<dim3(12, 32), 256>>>(p_bsn, w_q, nullptr, p_q, 0);
    k_gemm<<<dim3(12, 32), 256>>>(p_bsn, w_k, nullptr, p_k, 0);
    k_gemm<<<dim3(12, 32), 256>>>(p_bsn, w_v, nullptr, p_v, 0);
    k_rms<<<NB * SS * HN / 8, 256>>>(p_q, rqw);
    k_rms<<<NB * SS * HN / 8, 256>>>(p_k, rkw);
    k_attn<<<dim3(16, HN, NB), 256>>>(beta);
    k_gemm<<<dim3(12, 32), 256>>>(p_attn, w_o, b_o, out, 2);
}

// round 2
// speedup vs baseline: 1.0311x; 1.0311x over previous
#include <cuda_runtime.h>
#include <math.h>

#define SS   1024
#define CS   768
#define C3   2304
#define CZ   128
#define HN   24
#define DD   32
#define NB   2
#define LEPS 1e-5f
#define NINF 1.0e9f

typedef unsigned long long u64;

__device__ __forceinline__ void fma2(u64 &d, u64 a, u64 b) {
    asm("fma.rn.f32x2 %0, %1, %2, %0;" : "+l"(d) : "l"(a), "l"(b));
}
__device__ __forceinline__ u64 mul2(u64 a, u64 b) {
    u64 d; asm("mul.rn.f32x2 %0, %1, %2;" : "=l"(d) : "l"(a), "l"(b)); return d;
}
__device__ __forceinline__ u64 bc2(float x) {
    u64 d; asm("mov.b64 %0, {%1, %1};" : "=l"(d) : "f"(x)); return d;
}
__device__ __forceinline__ float2 unp(u64 v) {
    float2 r; asm("mov.b64 {%0, %1}, %2;" : "=f"(r.x), "=f"(r.y) : "l"(v)); return r;
}

// ---------------- device scratch ----------------
__device__ float g_emb [NB * 3 * CS];
__device__ float g_bsn [NB * SS * CS];
__device__ float g_qkv [NB * SS * C3];          // [q|k|v] fused
__device__ float g_attn[NB * SS * CS];
__device__ float g_bias[(size_t)HN * SS * SS];  // includes mask

// ---------------- adaLN embedding ----------------
__global__ void k_adaln(const float* __restrict__ t,
                        const float* __restrict__ w,
                        const float* __restrict__ bvec) {
    __shared__ float st[CS];
    int b = blockIdx.y;
    for (int c = threadIdx.x; c < CS; c += blockDim.x) {
        float x = t[b * CS + c];
        st[c] = x / (1.f + __expf(-x));
    }
    __syncthreads();
    int j = blockIdx.x * blockDim.x + threadIdx.x;
    if (j < 3 * CS) {
        float acc = bvec[j];
        for (int c = 0; c < CS; c++)
            acc += st[c] * w[(size_t)c * (3 * CS) + j];
        g_emb[b * 3 * CS + j] = acc;
    }
}

// ---------------- bs LayerNorm + adaLN modulation ----------------
__global__ void k_bsnorm(const float* __restrict__ bs) {
    int row = blockIdx.x;
    int b = row / SS;
    const float* x = bs + (size_t)row * CS;
    float* y = g_bsn + (size_t)row * CS;
    __shared__ float red[32];
    float lx[3];
    float s = 0.f, ss = 0.f;
#pragma unroll
    for (int i = 0; i < 3; i++) {
        float v = x[threadIdx.x + i * 256];
        lx[i] = v; s += v; ss += v * v;
    }
#pragma unroll
    for (int off = 16; off; off >>= 1) {
        s  += __shfl_xor_sync(0xffffffffu, s,  off);
        ss += __shfl_xor_sync(0xffffffffu, ss, off);
    }
    int wi = threadIdx.x >> 5;
    if ((threadIdx.x & 31) == 0) { red[wi] = s; red[8 + wi] = ss; }
    __syncthreads();
    if (threadIdx.x < 32) {
        s  = (threadIdx.x < 8) ? red[threadIdx.x]     : 0.f;
        ss = (threadIdx.x < 8) ? red[8 + threadIdx.x] : 0.f;
#pragma unroll
        for (int off = 4; off; off >>= 1) {
            s  += __shfl_xor_sync(0xffffffffu, s,  off);
            ss += __shfl_xor_sync(0xffffffffu, ss, off);
        }
        if (threadIdx.x == 0) { red[16] = s; red[17] = ss; }
    }
    __syncthreads();
    float mu  = red[16] / (float)CS;
    float var = red[17] / (float)CS - mu * mu;
    float rs  = rsqrtf(var + LEPS);
    const float* shv = g_emb + b * 3 * CS;
    const float* scv = g_emb + b * 3 * CS + CS;
#pragma unroll
    for (int i = 0; i < 3; i++) {
        int c = threadIdx.x + i * 256;
        y[c] = (lx[i] - mu) * rs * (1.f + scv[c]) + shv[c];
    }
}

// ---------------- 128x128-tile f32x2 GEMM ----------------
// A[M x 768] @ Bsel[768 x 768] -> C (ldc), N covered by up to 3 B matrices.
// mode 0: C = A@B ; mode 2: C = (A@B + bvec) * gate
__global__ void __launch_bounds__(256, 2)
k_gemm128(const float* __restrict__ A,
          const float* __restrict__ B0, const float* __restrict__ B1,
          const float* __restrict__ B2, const float* __restrict__ bvec,
          float* __restrict__ C, int ldc, int mode) {
    __shared__ float As[16][128];
    __shared__ float Bs[16][128];
    int n0c = blockIdx.x * 128;               // column in C
    int sel = n0c / CS;
    const float* B = (sel == 0) ? B0 : (sel == 1) ? B1 : B2;
    int nb = n0c - sel * CS;                  // column in B
    int m0 = blockIdx.y * 128;
    int tid = threadIdx.x;
    int tx = tid & 15, ty = tid >> 4;

    u64 acc[8][4];
#pragma unroll
    for (int r = 0; r < 8; r++)
#pragma unroll
        for (int c = 0; c < 4; c++) acc[r][c] = 0ull;

    int arow = tid >> 1;
    int akb  = (tid & 1) * 8;

    for (int k0 = 0; k0 < CS; k0 += 16) {
#pragma unroll
        for (int i = 0; i < 2; i++) {
            int koff = akb + i * 4;
            float4 v = *(const float4*)(A + (size_t)(m0 + arow) * CS + k0 + koff);
            As[koff + 0][arow] = v.x; As[koff + 1][arow] = v.y;
            As[koff + 2][arow] = v.z; As[koff + 3][arow] = v.w;
        }
#pragma unroll
        for (int i = 0; i < 2; i++) {
            int idx = tid + i * 256;
            int kk = idx >> 5, n4 = (idx & 31) * 4;
            float4 v = *(const float4*)(B + (size_t)(k0 + kk) * CS + nb + n4);
            *(float4*)&Bs[kk][n4] = v;
        }
        __syncthreads();
#pragma unroll
        for (int kk = 0; kk < 16; kk++) {
            float4 a0 = *(const float4*)&As[kk][ty * 8];
            float4 a1 = *(const float4*)&As[kk][ty * 8 + 4];
            const u64* bp = (const u64*)&Bs[kk][tx * 8];
            u64 b0 = bp[0], b1 = bp[1], b2 = bp[2], b3 = bp[3];
            u64 ar[8];
            ar[0] = bc2(a0.x); ar[1] = bc2(a0.y); ar[2] = bc2(a0.z); ar[3] = bc2(a0.w);
            ar[4] = bc2(a1.x); ar[5] = bc2(a1.y); ar[6] = bc2(a1.z); ar[7] = bc2(a1.w);
#pragma unroll
            for (int r = 0; r < 8; r++) {
                fma2(acc[r][0], ar[r], b0);
                fma2(acc[r][1], ar[r], b1);
                fma2(acc[r][2], ar[r], b2);
                fma2(acc[r][3], ar[r], b3);
            }
        }
        __syncthreads();
    }
#pragma unroll
    for (int r = 0; r < 8; r++) {
        int m = m0 + ty * 8 + r;
        int b = m >> 10;
        const float* gate = g_emb + b * 3 * CS + 2 * CS;
#pragma unroll
        for (int cj = 0; cj < 4; cj++) {
            float2 v = unp(acc[r][cj]);
            int n = n0c + tx * 8 + cj * 2;
            if (mode == 2) {
                v.x = (v.x + bvec[n + 0]) * gate[n + 0];
                v.y = (v.y + bvec[n + 1]) * gate[n + 1];
            }
            *(float2*)(C + (size_t)m * ldc + n) = v;
        }
    }
}

// ---------------- per-head RMS norm (in place, qkv layout) ----------------
__global__ void k_rms(float* __restrict__ x, const float* __restrict__ w, int off) {
    int gw = blockIdx.x * (blockDim.x >> 5) + (threadIdx.x >> 5);
    int lane = threadIdx.x & 31;
    if (gw >= NB * SS * HN) return;
    int row = gw / HN, h = gw % HN;
    size_t idx = (size_t)row * C3 + off + h * DD + lane;
    float v = x[idx];
    float ss = v * v;
#pragma unroll
    for (int o = 16; o; o >>= 1)
        ss += __shfl_xor_sync(0xffffffffu, ss, o);
    x[idx] = v * rsqrtf(ss / (float)DD + LEPS) * w[lane];
}

// ---------------- bias: LN(z) @ w_z + mask (f32x2) ----------------
// block = 128 pairs, 128 threads, dyn smem 80KB
__global__ void k_bias2(const float* __restrict__ z, const int* __restrict__ zmask,
                        const float* __restrict__ lnw, const float* __restrict__ lnb,
                        const float* __restrict__ wz) {
    extern __shared__ float sm[];
    float* sz    = sm;                    // 128 * 132
    float* swzT  = sm + 128 * 132;        // 24 * 128
    float* smu   = swzT + 24 * 128;       // 128
    float* srs   = smu + 128;             // 128
    float* slnwb = srs + 128;             // 256
    int tid = threadIdx.x;
    int pbase = blockIdx.x * 128;

    for (int i = tid; i < CZ * HN; i += 128) {
        int c = i / HN, h = i - c * HN;
        swzT[h * 128 + c] = wz[i];
    }
    slnwb[tid] = lnw[tid];
    slnwb[128 + tid] = lnb[tid];

    // load own row + stats
    {
        const float4* zr = (const float4*)(z + (size_t)(pbase + tid) * CZ);
        float* dst = sz + tid * 132;
        float s = 0.f, ssum = 0.f;
#pragma unroll 8
        for (int i = 0; i < 32; i++) {
            float4 v = zr[i];
            s += v.x + v.y + v.z + v.w;
            ssum += v.x * v.x + v.y * v.y + v.z * v.z + v.w * v.w;
            *(float4*)(dst + i * 4) = v;
        }
        float mu = s * (1.f / 128.f);
        smu[tid] = mu;
        srs[tid] = rsqrtf(ssum * (1.f / 128.f) - mu * mu + LEPS);
    }
    __syncthreads();
    // cooperative normalize
    for (int i = tid; i < 128 * 64; i += 128) {
        int r = i >> 6, c2 = (i & 63) * 2;
        float2 v = *(float2*)(sz + r * 132 + c2);
        float mu = smu[r], rs = srs[r];
        float2 w = *(const float2*)(slnwb + c2);
        float2 bb = *(const float2*)(slnwb + 128 + c2);
        v.x = (v.x - mu) * rs * w.x + bb.x;
        v.y = (v.y - mu) * rs * w.y + bb.y;
        *(float2*)(sz + r * 132 + c2) = v;
    }
    __syncthreads();
    // GEMM: thread tile = 8 pairs x 3 heads, packed along c
    int pg = tid & 15, hg = tid >> 4;
    u64 acc[8][3];
#pragma unroll
    for (int i = 0; i < 8; i++)
#pragma unroll
        for (int j = 0; j < 3; j++) acc[i][j] = 0ull;
    const float* zb = sz + pg * 132;
    const float* wb = swzT + hg * 3 * 128;
#pragma unroll 4
    for (int c = 0; c < 128; c += 2) {
        u64 w0 = *(const u64*)(wb + c);
        u64 w1 = *(const u64*)(wb + 128 + c);
        u64 w2 = *(const u64*)(wb + 256 + c);
#pragma unroll
        for (int i = 0; i < 8; i++) {
            u64 zv = *(const u64*)(zb + i * 16 * 132 + c);
            fma2(acc[i][0], zv, w0);
            fma2(acc[i][1], zv, w1);
            fma2(acc[i][2], zv, w2);
        }
    }
#pragma unroll
    for (int i = 0; i < 8; i++) {
        int pair = pbase + pg + 16 * i;
        float madd = (zmask[pair] > 0) ? 0.f : -NINF;
#pragma unroll
        for (int j = 0; j < 3; j++) {
            float2 u = unp(acc[i][j]);
            g_bias[(size_t)(hg * 3 + j) * SS * SS + pair] = u.x + u.y + madd;
        }
    }
}

// ---------------- attention (flash-style, f32x2) ----------------
__global__ void __launch_bounds__(256, 2) k_attn(const float* __restrict__ beta) {
    __shared__ float sq[64][36];
    __shared__ float sk[64][36];
    __shared__ float svT[32][68];
    __shared__ float sp[64][68];
    int qt = blockIdx.x, h = blockIdx.y, b = blockIdx.z;
    int q0 = qt * 64;
    int tid = threadIdx.x, tx = tid & 15, ty = tid >> 4;
#pragma unroll
    for (int i = 0; i < 2; i++) {
        int lin = tid + i * 256;
        int r = lin >> 3, d4 = (lin & 7) * 4;
        float4 v = *(const float4*)(g_qkv + (size_t)(b * SS + q0 + r) * C3 + h * DD + d4);
        *(float4*)&sq[r][d4] = v;
    }
    float m[4], l[4];
    u64 o2[4][2];
#pragma unroll
    for (int r = 0; r < 4; r++) {
        m[r] = -1e30f; l[r] = 0.f; o2[r][0] = 0ull; o2[r][1] = 0ull;
    }
    const float sc = 0.17677669529663687f;

    for (int kt = 0; kt < 16; kt++) {
        int k0 = kt * 64;
        __syncthreads();
#pragma unroll
        for (int i = 0; i < 2; i++) {
            int lin = tid + i * 256;
            int r = lin >> 3, d4 = (lin & 7) * 4;
            float4 kv4 = *(const float4*)(g_qkv + (size_t)(b * SS + k0 + r) * C3 + CS + h * DD + d4);
            *(float4*)&sk[r][d4] = kv4;
            float4 vv4 = *(const float4*)(g_qkv + (size_t)(b * SS + k0 + r) * C3 + 2 * CS + h * DD + d4);
            svT[d4 + 0][r] = vv4.x; svT[d4 + 1][r] = vv4.y;
            svT[d4 + 2][r] = vv4.z; svT[d4 + 3][r] = vv4.w;
        }
        __syncthreads();
        // GEMM1: s = q @ k^T, packed along d
        u64 s2[4][4];
#pragma unroll
        for (int r = 0; r < 4; r++)
#pragma unroll
            for (int c = 0; c < 4; c++) s2[r][c] = 0ull;
#pragma unroll
        for (int d = 0; d < DD; d += 4) {
            ulonglong2 qv[4], kv[4];
#pragma unroll
            for (int r = 0; r < 4; r++) qv[r] = *(const ulonglong2*)&sq[ty * 4 + r][d];
#pragma unroll
            for (int c = 0; c < 4; c++) kv[c] = *(const ulonglong2*)&sk[tx * 4 + c][d];
#pragma unroll
            for (int r = 0; r < 4; r++)
#pragma unroll
                for (int c = 0; c < 4; c++) {
                    fma2(s2[r][c], qv[r].x, kv[c].x);
                    fma2(s2[r][c], qv[r].y, kv[c].y);
                }
        }
        float s[4][4];
#pragma unroll
        for (int r = 0; r < 4; r++) {
            int qi = q0 + ty * 4 + r;
            float4 bz = *(const float4*)(g_bias + (size_t)h * SS * SS + (size_t)qi * SS + k0 + tx * 4);
            float4 bt = *(const float4*)(beta   + (size_t)b * SS * SS + (size_t)qi * SS + k0 + tx * 4);
            float2 u0 = unp(s2[r][0]);
            float2 u1 = unp(s2[r][1]);
            float2 u2 = unp(s2[r][2]);
            float2 u3 = unp(s2[r][3]);
            s[r][0] = (u0.x + u0.y) * sc + bz.x + bt.x;
            s[r][1] = (u1.x + u1.y) * sc + bz.y + bt.y;
            s[r][2] = (u2.x + u2.y) * sc + bz.z + bt.z;
            s[r][3] = (u3.x + u3.y) * sc + bz.w + bt.w;
        }
        // online softmax
#pragma unroll
        for (int r = 0; r < 4; r++) {
            float mt = fmaxf(fmaxf(s[r][0], s[r][1]), fmaxf(s[r][2], s[r][3]));
#pragma unroll
            for (int off = 8; off; off >>= 1)
                mt = fmaxf(mt, __shfl_xor_sync(0xffffffffu, mt, off));
            float mn = fmaxf(m[r], mt);
            float alpha = __expf(m[r] - mn);
            float p0 = __expf(s[r][0] - mn);
            float p1 = __expf(s[r][1] - mn);
            float p2 = __expf(s[r][2] - mn);
            float p3 = __expf(s[r][3] - mn);
            float rsum = p0 + p1 + p2 + p3;
#pragma unroll
            for (int off = 8; off; off >>= 1)
                rsum += __shfl_xor_sync(0xffffffffu, rsum, off);
            l[r] = l[r] * alpha + rsum;
            m[r] = mn;
            u64 av = bc2(alpha);
            o2[r][0] = mul2(o2[r][0], av);
            o2[r][1] = mul2(o2[r][1], av);
            sp[ty * 4 + r][tx * 4 + 0] = p0;
            sp[ty * 4 + r][tx * 4 + 1] = p1;
            sp[ty * 4 + r][tx * 4 + 2] = p2;
            sp[ty * 4 + r][tx * 4 + 3] = p3;
        }
        __syncthreads();
        // GEMM2: o += p @ v, packed along kk (vT)
#pragma unroll 4
        for (int kk = 0; kk < 64; kk += 4) {
            ulonglong2 pv[4];
#pragma unroll
            for (int r = 0; r < 4; r++) pv[r] = *(const ulonglong2*)&sp[ty * 4 + r][kk];
            ulonglong2 vv[2];
#pragma unroll
            for (int j = 0; j < 2; j++) vv[j] = *(const ulonglong2*)&svT[tx * 2 + j][kk];
#pragma unroll
            for (int r = 0; r < 4; r++)
#pragma unroll
                for (int j = 0; j < 2; j++) {
                    fma2(o2[r][j], pv[r].x, vv[j].x);
                    fma2(o2[r][j], pv[r].y, vv[j].y);
                }
        }
    }
#pragma unroll
    for (int r = 0; r < 4; r++) {
        float inv = 1.f / l[r];
        int qi = q0 + ty * 4 + r;
        float* dst = g_attn + (size_t)(b * SS + qi) * CS + h * DD + tx * 2;
        float2 u0 = unp(o2[r][0]);
        float2 u1 = unp(o2[r][1]);
        dst[0] = (u0.x + u0.y) * inv;
        dst[1] = (u1.x + u1.y) * inv;
    }
}

// ---------------- launch ----------------
extern "C" void kernel_launch(void* const* d_in, const int* in_sizes, int n_in,
                              void* d_out, int out_size) {
    const float* bs      = (const float*)d_in[0];
    const float* z       = (const float*)d_in[1];
    const float* t       = (const float*)d_in[2];
    const float* beta    = (const float*)d_in[3];
    const int*   zmask   = (const int*)  d_in[4];
    const float* w_adaln = (const float*)d_in[5];
    const float* b_adaln = (const float*)d_in[6];
    const float* lnw     = (const float*)d_in[7];
    const float* lnb     = (const float*)d_in[8];
    const float* w_q     = (const float*)d_in[9];
    const float* w_k     = (const float*)d_in[10];
    const float* w_v     = (const float*)d_in[11];
    const float* w_z     = (const float*)d_in[12];
    const float* rqw     = (const float*)d_in[13];
    const float* rkw     = (const float*)d_in[14];
    const float* w_o     = (const float*)d_in[15];
    const float* b_o     = (const float*)d_in[16];
    float* out = (float*)d_out;

    float *p_bsn, *p_qkv, *p_attn;
    cudaGetSymbolAddress((void**)&p_bsn,  g_bsn);
    cudaGetSymbolAddress((void**)&p_qkv,  g_qkv);
    cudaGetSymbolAddress((void**)&p_attn, g_attn);

    static int configured = 0;
    if (!configured) {
        cudaFuncSetAttribute(k_bias2, cudaFuncAttributeMaxDynamicSharedMemorySize, 82000);
        configured = 1;
    }

    k_adaln<<<dim3(9, 2), 256>>>(t, w_adaln, b_adaln);
    k_bias2<<<SS * SS / 128, 128, 81920>>>(z, zmask, lnw, lnb, w_z);
    k_bsnorm<<<NB * SS, 256>>>(bs);
    k_gemm128<<<dim3(18, 16), 256>>>(p_bsn, w_q, w_k, w_v, nullptr, p_qkv, C3, 0);
    k_rms<<<NB * SS * HN / 8, 256>>>(p_qkv, rqw, 0);
    k_rms<<<NB * SS * HN / 8, 256>>>(p_qkv, rkw, CS);
    k_attn<<<dim3(16, HN, NB), 256>>>(beta);
    k_gemm128<<<dim3(6, 16), 256>>>(p_attn, w_o, w_o, w_o, b_o, out, CS, 2);
}